// round 11
// baseline (speedup 1.0000x reference)
#include <cuda_runtime.h>
#include <cstdint>

#define TOPK     5
#define ROWS     112                 // x rows per CTA -> grid 147 = one CTA/SM, single wave
#define PSPLIT   8                   // p-range split groups -> 896 threads, 28 warps
#define PPT      13                  // points per group (8*13 = 104 = padded NP)
#define NP       100
#define NPPAD    104
#define NTHREADS (ROWS * PSPLIT)     // 896

#define XS_BYTES  (ROWS * 1024)      // 114688: x tile, swizzled, 1KB row stride
#define RF_BYTES  (NPPAD * 1024)     // 106496: negated ref (+4 pad rows of -1e18)
#define SMEM_BYTES (XS_BYTES + RF_BYTES)   // 221184 B (<= 232448 cap)

typedef unsigned long long u64;

__device__ __forceinline__ u64 f32x2_add(u64 a, u64 b) {
    u64 r; asm("add.rn.f32x2 %0, %1, %2;" : "=l"(r) : "l"(a), "l"(b)); return r;
}
__device__ __forceinline__ u64 f32x2_fma(u64 a, u64 b, u64 c) {
    u64 r; asm("fma.rn.f32x2 %0, %1, %2, %3;" : "=l"(r) : "l"(a), "l"(b), "l"(c)); return r;
}
__device__ __forceinline__ void lds_v2u64(uint32_t addr, u64& a, u64& b) {
    asm volatile("ld.shared.v2.u64 {%0, %1}, [%2];" : "=l"(a), "=l"(b) : "r"(addr));
}
__device__ __forceinline__ float2 unpk(u64 v) {
    float2 f; asm("mov.b64 {%0, %1}, %2;" : "=f"(f.x), "=f"(f.y) : "l"(v)); return f;
}

__device__ __forceinline__ void topk_insert(float dist, int idx, float* bd, int* bi) {
    // ascending p + strict '<'  ==  lax.top_k lowest-index-first tie break
    if (dist < bd[TOPK - 1]) {
        bd[TOPK - 1] = dist; bi[TOPK - 1] = idx;
#pragma unroll
        for (int t = TOPK - 1; t >= 1; --t) {
            if (bd[t] < bd[t - 1]) {
                float tf = bd[t]; bd[t] = bd[t - 1]; bd[t - 1] = tf;
                int   ti = bi[t]; bi[t] = bi[t - 1]; bi[t - 1] = ti;
            }
        }
    }
}

// One j-chunk for a sub-batch of NB points: batched loads, then batched math.
// Accumulation per point stays accA (classes 0,1) / accB (classes 2,3) in
// ascending-j order -> bit-identical to the proven Round-4 tree.
template<int NB>
__device__ __forceinline__ void batch_step(
    u64 xl, u64 xh, uint32_t raddr, u64* accA, u64* accB)
{
    u64 rl[NB], rh[NB];
#pragma unroll
    for (int b = 0; b < NB; ++b)
        lds_v2u64(raddr + (uint32_t)(b * 1024), rl[b], rh[b]);   // broadcast batch
#pragma unroll
    for (int b = 0; b < NB; ++b) {
        u64 dl = f32x2_add(xl, rl[b]);       // (d0, d1) = x + (-r)
        u64 dh = f32x2_add(xh, rh[b]);       // (d2, d3)
        accA[b] = f32x2_fma(dl, dl, accA[b]);
        accB[b] = f32x2_fma(dh, dh, accB[b]);
    }
}

// Diff-square for PB points (PB = 7 or 6), sub-batched 4 + (PB-4).
template<int PB>
__device__ __forceinline__ void compute_block(
    uint32_t xbase, uint32_t xorm, uint32_t rb0, int pbase,
    float* bd, int* bi)
{
    u64 accA[PB], accB[PB];
#pragma unroll
    for (int pp = 0; pp < PB; ++pp) { accA[pp] = 0ULL; accB[pp] = 0ULL; }

#pragma unroll 4
    for (int j = 0; j < 64; ++j) {               // 64 x 16B chunks over D=256
        u64 xl, xh;
        lds_v2u64(xbase + (((uint32_t)(j * 16)) ^ xorm), xl, xh);
        const uint32_t ra = rb0 + (uint32_t)(j * 16);
        batch_step<4>(xl, xh, ra, accA, accB);
        batch_step<PB - 4>(xl, xh, ra + 4u * 1024u, accA + 4, accB + 4);
    }

#pragma unroll
    for (int pp = 0; pp < PB; ++pp) {
        float2 a = unpk(accA[pp]);
        float2 b = unpk(accB[pp]);
        float dist = (a.x + a.y) + (b.x + b.y);  // Round-4 exact tree
        topk_insert(dist, pbase + pp, bd, bi);
    }
}

__global__ void __launch_bounds__(NTHREADS)
knn_topk_kernel(const float* __restrict__ x,
                const float* __restrict__ ref,
                float* __restrict__ out,     // indices as float32 (__output__ dtype!)
                int B)
{
    extern __shared__ unsigned char smem[];
    const uint32_t s0 = (uint32_t)__cvta_generic_to_shared(smem);

    const int tid  = threadIdx.x;
    const int row0 = blockIdx.x * ROWS;
    const int nrows = (B - row0) < ROWS ? (B - row0) : ROWS;

    // ---- stage x tile, XOR-swizzled (float4 col c -> c ^ (r&7)) ----
    {
        const float4* x4 = (const float4*)x;
        for (int i = tid; i < ROWS * 64; i += NTHREADS) {
            int rr = i >> 6, c = i & 63;
            if (rr < nrows) {
                uint32_t off = (uint32_t)(rr * 1024) + (uint32_t)((c ^ (rr & 7)) * 16);
                *(float4*)(smem + off) = x4[(size_t)(row0 + rr) * 64 + c];
            }
        }
    }
    // ---- stage NEGATED ref; pad rows 100..103 with -1e18 (never in top-k) ----
    {
        const float4* r4 = (const float4*)ref;
        for (int i = tid; i < NPPAD * 64; i += NTHREADS) {
            int p = i >> 6, c = i & 63;
            float4 v;
            if (p < NP) {
                v = r4[p * 64 + c];
                v.x = -v.x; v.y = -v.y; v.z = -v.z; v.w = -v.w;
            } else {
                v.x = v.y = v.z = v.w = -1e18f;
            }
            *(float4*)(smem + XS_BYTES + (uint32_t)(p * 1024 + c * 16)) = v;
        }
    }
    __syncthreads();

    const int r = tid % ROWS;        // row within tile
    const int g = tid / ROWS;        // p-split group 0..7
    const int p0 = g * PPT;

    const float INF = __int_as_float(0x7f800000);
    float bd[TOPK]; int bi[TOPK];
#pragma unroll
    for (int j = 0; j < TOPK; ++j) { bd[j] = INF; bi[j] = 0; }

    if (r < nrows) {
        const uint32_t xbase = s0 + (uint32_t)(r * 1024);
        const uint32_t xorm  = (uint32_t)(r & 7) << 4;
        const uint32_t rb0   = s0 + XS_BYTES + (uint32_t)(p0 * 1024);

        compute_block<7>(xbase, xorm, rb0,             p0,     bd, bi);
        compute_block<6>(xbase, xorm, rb0 + 7u * 1024u, p0 + 7, bd, bi);
    }

    // ---- merge 8 partial top-5 lists per row (reuse ref SMEM region) ----
    __syncthreads();
    float* mf = (float*)(smem + XS_BYTES);
    int*   mi = (int*)(smem + XS_BYTES + (PSPLIT - 1) * ROWS * TOPK * sizeof(float));

    if (g >= 1 && r < nrows) {
        int base = ((g - 1) * ROWS + r) * TOPK;
#pragma unroll
        for (int j = 0; j < TOPK; ++j) { mf[base + j] = bd[j]; mi[base + j] = bi[j]; }
    }
    __syncthreads();

    if (g == 0 && r < nrows) {
        for (int gg = 1; gg < PSPLIT; ++gg) {
            int base = ((gg - 1) * ROWS + r) * TOPK;
#pragma unroll
            for (int j = 0; j < TOPK; ++j)
                topk_insert(mf[base + j], mi[base + j], bd, bi);
        }
        float* o = out + (size_t)(row0 + r) * TOPK;
#pragma unroll
        for (int j = 0; j < TOPK; ++j) o[j] = (float)bi[j];
    }
}

extern "C" void kernel_launch(void* const* d_in, const int* in_sizes, int n_in,
                              void* d_out, int out_size)
{
    const float* a = (const float*)d_in[0];
    const float* b = (const float*)d_in[1];
    const float* x   = (in_sizes[0] >= in_sizes[1]) ? a : b;
    const float* ref = (in_sizes[0] >= in_sizes[1]) ? b : a;
    int B = out_size / TOPK;                     // 16384

    float* out = (float*)d_out;
    cudaFuncSetAttribute(knn_topk_kernel,
                         cudaFuncAttributeMaxDynamicSharedMemorySize, SMEM_BYTES);
    int grid = (B + ROWS - 1) / ROWS;            // 147 -> one CTA per SM
    knn_topk_kernel<<<grid, NTHREADS, SMEM_BYTES>>>(x, ref, out, B);
}